// round 4
// baseline (speedup 1.0000x reference)
#include <cuda_runtime.h>
#include <cuda_bf16.h>
#include <mma.h>
#include <cstdint>

using namespace nvcuda;

#define T_TOK  2048
#define H_DIM  1024
#define N_EXP  16
#define I_DIM  512
#define SI_DIM 1024
#define TOPK   4
#define RTOT   (T_TOK * TOPK)            // 8192 assignments
#define RCAP   (RTOT + N_EXP * 128)      // padded capacity (each expert aligned to 128)

// ---------------- scratch (__device__ globals; no allocation allowed) ----------------
__device__ float g_topk_w[RTOT];
__device__ int   g_topk_idx[RTOT];
__device__ int   g_counts[N_EXP];
__device__ int   g_offsets[N_EXP];       // PADDED base offsets (multiples of 128)
__device__ int   g_cursor[N_EXP];
__device__ int   g_perm[RCAP];           // perm[padded slot] = t*4 + k, grouped by expert
__device__ float g_act[(size_t)RCAP * I_DIM];      // routed silu(g)*u rows (padded layout)
__device__ float g_ya[(size_t)RTOT * H_DIM];       // per-assignment expert output rows
__device__ float g_shact[(size_t)T_TOK * SI_DIM];  // shared-expert silu(g)*u

// ---------------- helpers ----------------
__device__ __forceinline__ void tf32_split(float v, float& hi, float& lo) {
    hi = wmma::__float_to_tf32(v);
    lo = wmma::__float_to_tf32(v - hi);
}

// ---------------- small kernels ----------------
__global__ void k_init() {
    int i = threadIdx.x;
    if (i < N_EXP) { g_counts[i] = 0; g_cursor[i] = 0; }
}

// scores = sigmoid(x @ gate_w^T); top-4; normalized weights; expert counts
__global__ void k_gate(const float* __restrict__ x, const float* __restrict__ gw) {
    __shared__ float sx[H_DIM];
    __shared__ float ssc[N_EXP];
    int t = blockIdx.x;
    const float* xr = x + (size_t)t * H_DIM;
    for (int i = threadIdx.x; i < H_DIM / 4; i += 128)
        ((float4*)sx)[i] = ((const float4*)xr)[i];
    __syncthreads();

    int warp = threadIdx.x >> 5, lane = threadIdx.x & 31;
    for (int e = warp; e < N_EXP; e += 4) {
        const float* w = gw + (size_t)e * H_DIM;
        float s = 0.f;
        for (int k = lane; k < H_DIM; k += 32) s += sx[k] * w[k];
        #pragma unroll
        for (int o = 16; o; o >>= 1) s += __shfl_xor_sync(0xffffffff, s, o);
        if (lane == 0) ssc[e] = 1.f / (1.f + expf(-s));
    }
    __syncthreads();

    if (threadIdx.x == 0) {
        float sc[N_EXP];
        #pragma unroll
        for (int e = 0; e < N_EXP; e++) sc[e] = ssc[e];
        int   idx[TOPK]; float wv[TOPK]; float sum = 0.f;
        #pragma unroll
        for (int k = 0; k < TOPK; k++) {
            int bi = 0; float bv = -1e30f;
            #pragma unroll
            for (int e = 0; e < N_EXP; e++)
                if (sc[e] > bv) { bv = sc[e]; bi = e; }   // strict > -> lowest index on ties
            idx[k] = bi; wv[k] = bv; sc[bi] = -1e31f; sum += bv;
        }
        float inv = 1.f / (sum + 1e-20f);
        #pragma unroll
        for (int k = 0; k < TOPK; k++) {
            g_topk_idx[t * TOPK + k] = idx[k];
            g_topk_w[t * TOPK + k]   = wv[k] * inv;
            atomicAdd(&g_counts[idx[k]], 1);
        }
    }
}

// padded offsets: each expert's region rounded up to 128 rows so full-tile
// epilogue stores never cross into the next expert's region (race fix).
__global__ void k_offsets() {
    int s = 0;
    for (int e = 0; e < N_EXP; e++) {
        g_offsets[e] = s;
        s += (g_counts[e] + 127) & ~127;
    }
}

__global__ void k_scatter() {
    int t = blockIdx.x * 256 + threadIdx.x;
    if (t >= T_TOK) return;
    #pragma unroll
    for (int k = 0; k < TOPK; k++) {
        int e = g_topk_idx[t * TOPK + k];
        int pos = atomicAdd(&g_cursor[e], 1);
        g_perm[g_offsets[e] + pos] = t * TOPK + k;
    }
}

// ---------------- SwiGLU GEMM (3xTF32): act = silu(A@Wg) * (A@Wu) ----------------
template<bool GATHER, int LDW>
__global__ __launch_bounds__(256) void k_swiglu_gemm(
    const float* __restrict__ X, const float* __restrict__ Wg, const float* __restrict__ Wu)
{
    constexpr int BM = 128, BN = 64, BK = 32;
    __shared__ float sA [BM][BK + 4];
    __shared__ float sBg[BK][BN + 4];
    __shared__ float sBu[BK][BN + 4];
    __shared__ int   sTok[BM];

    int nb = blockIdx.x, rb = blockIdx.y, e = blockIdx.z;
    int base = 0, cnt = T_TOK;
    if (GATHER) { base = g_offsets[e]; cnt = g_counts[e]; }
    int row0 = rb * BM;
    if (row0 >= cnt) return;
    int n0 = nb * BN;

    const float* wg = Wg;
    const float* wu = Wu;
    if (GATHER) { size_t off = (size_t)e * H_DIM * I_DIM; wg += off; wu += off; }

    int tid = threadIdx.x;
    if (tid < BM) {
        int local = row0 + tid;
        int tok;
        if (GATHER) tok = (local < cnt) ? (g_perm[base + local] >> 2) : 0;
        else        tok = local;
        sTok[tid] = tok;
    }
    __syncthreads();

    wmma::fragment<wmma::accumulator, 16, 16, 8, float> accG[2][2], accU[2][2];
    #pragma unroll
    for (int i = 0; i < 2; i++)
        #pragma unroll
        for (int j = 0; j < 2; j++) {
            wmma::fill_fragment(accG[i][j], 0.f);
            wmma::fill_fragment(accU[i][j], 0.f);
        }

    int warp = tid >> 5;
    int rowOff = (warp >> 1) * 32, colOff = (warp & 1) * 32;

    for (int k0 = 0; k0 < H_DIM; k0 += BK) {
        #pragma unroll
        for (int i = 0; i < 4; i++) {          // 128x32 A tile
            int lin = tid + i * 256;
            int r = lin >> 3, c4 = lin & 7;
            *(float4*)&sA[r][c4 * 4] =
                *(const float4*)(X + (size_t)sTok[r] * H_DIM + k0 + c4 * 4);
        }
        #pragma unroll
        for (int i = 0; i < 2; i++) {          // 32x64 B tiles
            int lin = tid + i * 256;
            int r = lin >> 4, c4 = lin & 15;
            *(float4*)&sBg[r][c4 * 4] =
                *(const float4*)(wg + (size_t)(k0 + r) * LDW + n0 + c4 * 4);
            *(float4*)&sBu[r][c4 * 4] =
                *(const float4*)(wu + (size_t)(k0 + r) * LDW + n0 + c4 * 4);
        }
        __syncthreads();
        #pragma unroll
        for (int kk = 0; kk < BK; kk += 8) {
            typedef wmma::fragment<wmma::matrix_a, 16, 16, 8, wmma::precision::tf32, wmma::row_major> FA;
            typedef wmma::fragment<wmma::matrix_b, 16, 16, 8, wmma::precision::tf32, wmma::row_major> FB;
            FA fah[2], fal[2];
            FB fgh[2], fgl[2], fuh[2], ful[2];
            #pragma unroll
            for (int i = 0; i < 2; i++) {
                wmma::load_matrix_sync(fah[i], &sA[rowOff + 16 * i][kk], BK + 4);
                #pragma unroll
                for (int s = 0; s < fah[i].num_elements; s++)
                    tf32_split(fah[i].x[s], fah[i].x[s], fal[i].x[s]);
            }
            #pragma unroll
            for (int j = 0; j < 2; j++) {
                wmma::load_matrix_sync(fgh[j], &sBg[kk][colOff + 16 * j], BN + 4);
                wmma::load_matrix_sync(fuh[j], &sBu[kk][colOff + 16 * j], BN + 4);
                #pragma unroll
                for (int s = 0; s < fgh[j].num_elements; s++) {
                    tf32_split(fgh[j].x[s], fgh[j].x[s], fgl[j].x[s]);
                    tf32_split(fuh[j].x[s], fuh[j].x[s], ful[j].x[s]);
                }
            }
            #pragma unroll
            for (int i = 0; i < 2; i++)
                #pragma unroll
                for (int j = 0; j < 2; j++) {
                    wmma::mma_sync(accG[i][j], fah[i], fgh[j], accG[i][j]);
                    wmma::mma_sync(accG[i][j], fah[i], fgl[j], accG[i][j]);
                    wmma::mma_sync(accG[i][j], fal[i], fgh[j], accG[i][j]);
                    wmma::mma_sync(accU[i][j], fah[i], fuh[j], accU[i][j]);
                    wmma::mma_sync(accU[i][j], fah[i], ful[j], accU[i][j]);
                    wmma::mma_sync(accU[i][j], fal[i], fuh[j], accU[i][j]);
                }
        }
        __syncthreads();
    }

    // Epilogue: silu(g)*u in registers; full-tile store is safe (padded layout)
    float* OutBase = GATHER ? g_act : g_shact;
    size_t orow0 = (size_t)(GATHER ? (base + row0) : row0);
    #pragma unroll
    for (int i = 0; i < 2; i++)
        #pragma unroll
        for (int j = 0; j < 2; j++) {
            #pragma unroll
            for (int s = 0; s < accG[i][j].num_elements; s++) {
                float g = accG[i][j].x[s];
                float u = accU[i][j].x[s];
                accG[i][j].x[s] = g * u / (1.f + __expf(-g));
            }
            float* p = OutBase + (orow0 + rowOff + 16 * i) * LDW + n0 + colOff + 16 * j;
            wmma::store_matrix_sync(p, accG[i][j], LDW, wmma::mem_row_major);
        }
}

// ---------------- down projection GEMM (3xTF32) ----------------
template<bool SCATTER, int LDA, int KDIM>
__global__ __launch_bounds__(256) void k_down_gemm(
    const float* __restrict__ W, float* __restrict__ OutP)
{
    constexpr int BM = 128, BN = 64, BK = 32;
    __shared__ __align__(16) char smem_raw[128 * 68 * 4];   // union
    float (*sA)[BK + 4] = (float(*)[BK + 4])smem_raw;
    float (*sB)[BN + 4] = (float(*)[BN + 4])(smem_raw + 128 * 36 * 4);
    float (*Ep)[BN + 4] = (float(*)[BN + 4])smem_raw;

    int nb = blockIdx.x, rb = blockIdx.y, e = blockIdx.z;
    int base = 0, cnt = T_TOK;
    if (SCATTER) { base = g_offsets[e]; cnt = g_counts[e]; }
    int row0 = rb * BM;
    if (row0 >= cnt) return;
    int n0 = nb * BN;

    const float* w = W;
    if (SCATTER) w += (size_t)e * I_DIM * H_DIM;
    const float* act = (SCATTER ? g_act : g_shact) + (size_t)(base + row0) * LDA;

    int tid = threadIdx.x;
    int warp = tid >> 5;
    int rowOff = (warp >> 1) * 32, colOff = (warp & 1) * 32;

    wmma::fragment<wmma::accumulator, 16, 16, 8, float> acc[2][2];
    #pragma unroll
    for (int i = 0; i < 2; i++)
        #pragma unroll
        for (int j = 0; j < 2; j++) wmma::fill_fragment(acc[i][j], 0.f);

    for (int k0 = 0; k0 < KDIM; k0 += BK) {
        #pragma unroll
        for (int i = 0; i < 4; i++) {
            int lin = tid + i * 256;
            int r = lin >> 3, c4 = lin & 7;
            *(float4*)&sA[r][c4 * 4] =
                *(const float4*)(act + (size_t)r * LDA + k0 + c4 * 4);
        }
        #pragma unroll
        for (int i = 0; i < 2; i++) {
            int lin = tid + i * 256;
            int r = lin >> 4, c4 = lin & 15;
            *(float4*)&sB[r][c4 * 4] =
                *(const float4*)(w + (size_t)(k0 + r) * H_DIM + n0 + c4 * 4);
        }
        __syncthreads();
        #pragma unroll
        for (int kk = 0; kk < BK; kk += 8) {
            typedef wmma::fragment<wmma::matrix_a, 16, 16, 8, wmma::precision::tf32, wmma::row_major> FA;
            typedef wmma::fragment<wmma::matrix_b, 16, 16, 8, wmma::precision::tf32, wmma::row_major> FB;
            FA fah[2], fal[2];
            FB fbh[2], fbl[2];
            #pragma unroll
            for (int i = 0; i < 2; i++) {
                wmma::load_matrix_sync(fah[i], &sA[rowOff + 16 * i][kk], BK + 4);
                #pragma unroll
                for (int s = 0; s < fah[i].num_elements; s++)
                    tf32_split(fah[i].x[s], fah[i].x[s], fal[i].x[s]);
            }
            #pragma unroll
            for (int j = 0; j < 2; j++) {
                wmma::load_matrix_sync(fbh[j], &sB[kk][colOff + 16 * j], BN + 4);
                #pragma unroll
                for (int s = 0; s < fbh[j].num_elements; s++)
                    tf32_split(fbh[j].x[s], fbh[j].x[s], fbl[j].x[s]);
            }
            #pragma unroll
            for (int i = 0; i < 2; i++)
                #pragma unroll
                for (int j = 0; j < 2; j++) {
                    wmma::mma_sync(acc[i][j], fah[i], fbh[j], acc[i][j]);
                    wmma::mma_sync(acc[i][j], fah[i], fbl[j], acc[i][j]);
                    wmma::mma_sync(acc[i][j], fal[i], fbh[j], acc[i][j]);
                }
        }
        __syncthreads();
    }

    // Epilogue: stage to smem, then per-row gated writeout
    #pragma unroll
    for (int i = 0; i < 2; i++)
        #pragma unroll
        for (int j = 0; j < 2; j++)
            wmma::store_matrix_sync(&Ep[rowOff + 16 * i][colOff + 16 * j],
                                    acc[i][j], BN + 4, wmma::mem_row_major);
    __syncthreads();
    #pragma unroll
    for (int i = 0; i < 8; i++) {
        int lin = tid + i * 256;          // 128 rows x 16 float4
        int r = lin >> 4, c4 = lin & 15;
        int local = row0 + r;
        if (SCATTER) {
            if (local < cnt) {
                int a = g_perm[base + local];
                *(float4*)(g_ya + (size_t)a * H_DIM + n0 + c4 * 4) = *(float4*)&Ep[r][c4 * 4];
            }
        } else {
            *(float4*)(OutP + (size_t)local * H_DIM + n0 + c4 * 4) = *(float4*)&Ep[r][c4 * 4];
        }
    }
}

// out[t] = shared_out[t] (already there) + sum_k w[t,k] * ya[t*4+k]
__global__ void k_combine(float* __restrict__ Out) {
    int lin = blockIdx.x * 256 + threadIdx.x;   // float4 index
    int t  = lin >> 8;                           // H/4 = 256 float4 per token
    int c4 = lin & 255;
    float4 acc = ((float4*)Out)[lin];
    #pragma unroll
    for (int k = 0; k < TOPK; k++) {
        float wv = g_topk_w[t * TOPK + k];
        float4 v = *(const float4*)(g_ya + (size_t)(t * TOPK + k) * H_DIM + c4 * 4);
        acc.x += wv * v.x; acc.y += wv * v.y; acc.z += wv * v.z; acc.w += wv * v.w;
    }
    ((float4*)Out)[lin] = acc;
}

// ---------------- launch ----------------
extern "C" void kernel_launch(void* const* d_in, const int* in_sizes, int n_in,
                              void* d_out, int out_size)
{
    const float* x  = (const float*)d_in[0];   // [1,2048,1024]
    const float* gw = (const float*)d_in[1];   // [16,1024]
    const float* eg = (const float*)d_in[2];   // [16,1024,512]
    const float* eu = (const float*)d_in[3];   // [16,1024,512]
    const float* ed = (const float*)d_in[4];   // [16,512,1024]
    const float* sg = (const float*)d_in[5];   // [1024,1024]
    const float* su = (const float*)d_in[6];   // [1024,1024]
    const float* sd = (const float*)d_in[7];   // [1024,1024]
    float* out = (float*)d_out;

    k_init<<<1, 32>>>();
    k_gate<<<T_TOK, 128>>>(x, gw);
    k_offsets<<<1, 1>>>();
    k_scatter<<<T_TOK / 256, 256>>>();

    // routed SwiGLU: grid (I/64, up-to-2048-rows/128, E)
    k_swiglu_gemm<true,  I_DIM ><<<dim3(I_DIM  / 64, 16,          N_EXP), 256>>>(x, eg, eu);
    // shared SwiGLU
    k_swiglu_gemm<false, SI_DIM><<<dim3(SI_DIM / 64, T_TOK / 128, 1    ), 256>>>(x, sg, su);

    // routed down -> scatter rows into g_ya
    k_down_gemm<true,  I_DIM,  I_DIM ><<<dim3(H_DIM / 64, 16,          N_EXP), 256>>>(ed, nullptr);
    // shared down -> writes d_out (covers every element)
    k_down_gemm<false, SI_DIM, SI_DIM><<<dim3(H_DIM / 64, T_TOK / 128, 1    ), 256>>>(sd, out);

    k_combine<<<(T_TOK * H_DIM / 4) / 256, 256>>>(out);
}

// round 5
// speedup vs baseline: 2.8360x; 2.8360x over previous
#include <cuda_runtime.h>
#include <cuda_bf16.h>
#include <mma.h>
#include <cstdint>

using namespace nvcuda;

#define T_TOK  2048
#define H_DIM  1024
#define N_EXP  16
#define I_DIM  512
#define SI_DIM 1024
#define TOPK   4
#define RTOT   (T_TOK * TOPK)            // 8192 assignments
#define RCAP   (RTOT + N_EXP * 128)      // padded capacity (each expert aligned to 128)

// ---------------- scratch (__device__ globals; no allocation allowed) ----------------
__device__ float g_topk_w[RTOT];
__device__ int   g_topk_idx[RTOT];
__device__ int   g_counts[N_EXP];
__device__ int   g_offsets[N_EXP];       // PADDED base offsets (multiples of 128)
__device__ int   g_cursor[N_EXP];
__device__ int   g_perm[RCAP];           // perm[padded slot] = t*4 + k, grouped by expert
__device__ float g_act[(size_t)RCAP * I_DIM];      // routed silu(g)*u rows (padded layout)
__device__ float g_ya[(size_t)RTOT * H_DIM];       // per-assignment expert output rows
__device__ float g_shact[(size_t)T_TOK * SI_DIM];  // shared-expert silu(g)*u

// ---------------- helpers ----------------
// Split 4 floats into bf16 hi + bf16 lo (error-free-ish: v = hi + lo + O(2^-18 v))
__device__ __forceinline__ void split4(float4 v, uint2& hi, uint2& lo) {
    __nv_bfloat162 h0 = __floats2bfloat162_rn(v.x, v.y);
    __nv_bfloat162 h1 = __floats2bfloat162_rn(v.z, v.w);
    float2 f0 = __bfloat1622float2(h0);
    float2 f1 = __bfloat1622float2(h1);
    __nv_bfloat162 l0 = __floats2bfloat162_rn(v.x - f0.x, v.y - f0.y);
    __nv_bfloat162 l1 = __floats2bfloat162_rn(v.z - f1.x, v.w - f1.y);
    hi.x = *(uint32_t*)&h0; hi.y = *(uint32_t*)&h1;
    lo.x = *(uint32_t*)&l0; lo.y = *(uint32_t*)&l1;
}

typedef wmma::fragment<wmma::matrix_a, 16, 16, 16, __nv_bfloat16, wmma::row_major> FragA;
typedef wmma::fragment<wmma::matrix_b, 16, 16, 16, __nv_bfloat16, wmma::row_major> FragB;
typedef wmma::fragment<wmma::accumulator, 16, 16, 16, float> FragC;

// ---------------- small kernels ----------------
__global__ void k_init() {
    int i = threadIdx.x;
    if (i < N_EXP) { g_counts[i] = 0; g_cursor[i] = 0; }
}

// scores = sigmoid(x @ gate_w^T); top-4; normalized weights; expert counts
__global__ void k_gate(const float* __restrict__ x, const float* __restrict__ gw) {
    __shared__ float sx[H_DIM];
    __shared__ float ssc[N_EXP];
    int t = blockIdx.x;
    const float* xr = x + (size_t)t * H_DIM;
    for (int i = threadIdx.x; i < H_DIM / 4; i += 128)
        ((float4*)sx)[i] = ((const float4*)xr)[i];
    __syncthreads();

    int warp = threadIdx.x >> 5, lane = threadIdx.x & 31;
    for (int e = warp; e < N_EXP; e += 4) {
        const float* w = gw + (size_t)e * H_DIM;
        float s = 0.f;
        for (int k = lane; k < H_DIM; k += 32) s += sx[k] * w[k];
        #pragma unroll
        for (int o = 16; o; o >>= 1) s += __shfl_xor_sync(0xffffffff, s, o);
        if (lane == 0) ssc[e] = 1.f / (1.f + expf(-s));
    }
    __syncthreads();

    if (threadIdx.x == 0) {
        float sc[N_EXP];
        #pragma unroll
        for (int e = 0; e < N_EXP; e++) sc[e] = ssc[e];
        int   idx[TOPK]; float wv[TOPK]; float sum = 0.f;
        #pragma unroll
        for (int k = 0; k < TOPK; k++) {
            int bi = 0; float bv = -1e30f;
            #pragma unroll
            for (int e = 0; e < N_EXP; e++)
                if (sc[e] > bv) { bv = sc[e]; bi = e; }   // strict > -> lowest index on ties
            idx[k] = bi; wv[k] = bv; sc[bi] = -1e31f; sum += bv;
        }
        float inv = 1.f / (sum + 1e-20f);
        #pragma unroll
        for (int k = 0; k < TOPK; k++) {
            g_topk_idx[t * TOPK + k] = idx[k];
            g_topk_w[t * TOPK + k]   = wv[k] * inv;
            atomicAdd(&g_counts[idx[k]], 1);
        }
    }
}

// padded offsets: each expert region rounded to 128 rows (full-tile stores stay inside)
__global__ void k_offsets() {
    int s = 0;
    for (int e = 0; e < N_EXP; e++) {
        g_offsets[e] = s;
        s += (g_counts[e] + 127) & ~127;
    }
}

__global__ void k_scatter() {
    int t = blockIdx.x * 256 + threadIdx.x;
    if (t >= T_TOK) return;
    #pragma unroll
    for (int k = 0; k < TOPK; k++) {
        int e = g_topk_idx[t * TOPK + k];
        int pos = atomicAdd(&g_cursor[e], 1);
        g_perm[g_offsets[e] + pos] = t * TOPK + k;
    }
}

// ---------------- SwiGLU GEMM (bf16x3): act = silu(A@Wg) * (A@Wu) ----------------
template<bool GATHER, int LDW>
__global__ __launch_bounds__(256) void k_swiglu_gemm(
    const float* __restrict__ X, const float* __restrict__ Wg, const float* __restrict__ Wu)
{
    constexpr int BM = 128, BN = 64, BK = 32;
    constexpr int LA = BK + 8;    // 40 bf16 = 80B rows (16B aligned)
    constexpr int LB = BN + 8;    // 72 bf16 = 144B rows
    __shared__ __nv_bfloat16 sAh[BM][LA], sAl[BM][LA];
    __shared__ __nv_bfloat16 sBgh[BK][LB], sBgl[BK][LB];
    __shared__ __nv_bfloat16 sBuh[BK][LB], sBul[BK][LB];
    __shared__ int sTok[BM];

    int nb = blockIdx.x, rb = blockIdx.y, e = blockIdx.z;
    int base = 0, cnt = T_TOK;
    if (GATHER) { base = g_offsets[e]; cnt = g_counts[e]; }
    int row0 = rb * BM;
    if (row0 >= cnt) return;
    int n0 = nb * BN;

    const float* wg = Wg;
    const float* wu = Wu;
    if (GATHER) { size_t off = (size_t)e * H_DIM * I_DIM; wg += off; wu += off; }

    int tid = threadIdx.x;
    if (tid < BM) {
        int local = row0 + tid;
        sTok[tid] = GATHER ? ((local < cnt) ? (g_perm[base + local] >> 2) : 0) : local;
    }
    __syncthreads();

    // per-thread global coords
    int aR = tid >> 3, aC = (tid & 7) * 4;     // A: rows aR + 32*i, cols aC (+k0)
    int bR = tid >> 4, bC = (tid & 15) * 4;    // B: rows bR + 16*i (+k0), cols n0+bC
    const float* aptr[4];
    #pragma unroll
    for (int i = 0; i < 4; i++)
        aptr[i] = X + (size_t)sTok[aR + 32 * i] * H_DIM + aC;
    const float* bg = wg + (size_t)bR * LDW + n0 + bC;
    const float* bu = wu + (size_t)bR * LDW + n0 + bC;

    float4 rA[4], rBg[2], rBu[2];
    #pragma unroll
    for (int i = 0; i < 4; i++) rA[i] = *(const float4*)(aptr[i]);
    #pragma unroll
    for (int i = 0; i < 2; i++) {
        rBg[i] = *(const float4*)(bg + (size_t)(i * 16) * LDW);
        rBu[i] = *(const float4*)(bu + (size_t)(i * 16) * LDW);
    }

    FragC accG[2][2], accU[2][2];
    #pragma unroll
    for (int i = 0; i < 2; i++)
        #pragma unroll
        for (int j = 0; j < 2; j++) {
            wmma::fill_fragment(accG[i][j], 0.f);
            wmma::fill_fragment(accU[i][j], 0.f);
        }

    int warp = tid >> 5;
    int rowOff = (warp >> 1) * 32, colOff = (warp & 1) * 32;

    for (int k0 = 0; k0 < H_DIM; k0 += BK) {
        // split regs -> smem
        #pragma unroll
        for (int i = 0; i < 4; i++) {
            uint2 h, l; split4(rA[i], h, l);
            int r = aR + 32 * i;
            *(uint2*)&sAh[r][aC] = h;
            *(uint2*)&sAl[r][aC] = l;
        }
        #pragma unroll
        for (int i = 0; i < 2; i++) {
            uint2 h, l;
            int r = bR + 16 * i;
            split4(rBg[i], h, l);
            *(uint2*)&sBgh[r][bC] = h; *(uint2*)&sBgl[r][bC] = l;
            split4(rBu[i], h, l);
            *(uint2*)&sBuh[r][bC] = h; *(uint2*)&sBul[r][bC] = l;
        }
        __syncthreads();

        // prefetch next tile (overlaps with MMA below)
        int k1 = k0 + BK;
        if (k1 < H_DIM) {
            #pragma unroll
            for (int i = 0; i < 4; i++) rA[i] = *(const float4*)(aptr[i] + k1);
            #pragma unroll
            for (int i = 0; i < 2; i++) {
                rBg[i] = *(const float4*)(bg + (size_t)(k1 + i * 16) * LDW);
                rBu[i] = *(const float4*)(bu + (size_t)(k1 + i * 16) * LDW);
            }
        }

        #pragma unroll
        for (int kk = 0; kk < BK; kk += 16) {
            FragA fah[2], fal[2];
            FragB fgh[2], fgl[2], fuh[2], ful[2];
            #pragma unroll
            for (int i = 0; i < 2; i++) {
                wmma::load_matrix_sync(fah[i], &sAh[rowOff + 16 * i][kk], LA);
                wmma::load_matrix_sync(fal[i], &sAl[rowOff + 16 * i][kk], LA);
            }
            #pragma unroll
            for (int j = 0; j < 2; j++) {
                wmma::load_matrix_sync(fgh[j], &sBgh[kk][colOff + 16 * j], LB);
                wmma::load_matrix_sync(fgl[j], &sBgl[kk][colOff + 16 * j], LB);
                wmma::load_matrix_sync(fuh[j], &sBuh[kk][colOff + 16 * j], LB);
                wmma::load_matrix_sync(ful[j], &sBul[kk][colOff + 16 * j], LB);
            }
            #pragma unroll
            for (int i = 0; i < 2; i++)
                #pragma unroll
                for (int j = 0; j < 2; j++) {
                    wmma::mma_sync(accG[i][j], fah[i], fgh[j], accG[i][j]);
                    wmma::mma_sync(accG[i][j], fah[i], fgl[j], accG[i][j]);
                    wmma::mma_sync(accG[i][j], fal[i], fgh[j], accG[i][j]);
                    wmma::mma_sync(accU[i][j], fah[i], fuh[j], accU[i][j]);
                    wmma::mma_sync(accU[i][j], fah[i], ful[j], accU[i][j]);
                    wmma::mma_sync(accU[i][j], fal[i], fuh[j], accU[i][j]);
                }
        }
        __syncthreads();
    }

    // Epilogue: silu(g)*u in registers; full-tile store safe (padded layout)
    float* OutBase = GATHER ? g_act : g_shact;
    size_t orow0 = (size_t)(GATHER ? (base + row0) : row0);
    #pragma unroll
    for (int i = 0; i < 2; i++)
        #pragma unroll
        for (int j = 0; j < 2; j++) {
            #pragma unroll
            for (int s = 0; s < accG[i][j].num_elements; s++) {
                float g = accG[i][j].x[s];
                float u = accU[i][j].x[s];
                accG[i][j].x[s] = g * u / (1.f + __expf(-g));
            }
            float* p = OutBase + (orow0 + rowOff + 16 * i) * LDW + n0 + colOff + 16 * j;
            wmma::store_matrix_sync(p, accG[i][j], LDW, wmma::mem_row_major);
        }
}

// ---------------- down projection GEMM (bf16x3) ----------------
template<bool SCATTER, int LDA, int KDIM>
__global__ __launch_bounds__(256) void k_down_gemm(
    const float* __restrict__ W, float* __restrict__ OutP)
{
    constexpr int BM = 128, BN = 64, BK = 32;
    constexpr int LA = BK + 8;    // 40
    constexpr int LB = BN + 8;    // 72
    // union: [sAh 10240][sAl 10240][sBh 4608][sBl 4608] = 29696B  vs  Ep 128*68*4 = 34816B
    __shared__ __align__(16) char smem_raw[34816];
    __nv_bfloat16 (*sAh)[LA] = (__nv_bfloat16(*)[LA])(smem_raw);
    __nv_bfloat16 (*sAl)[LA] = (__nv_bfloat16(*)[LA])(smem_raw + 10240);
    __nv_bfloat16 (*sBh)[LB] = (__nv_bfloat16(*)[LB])(smem_raw + 20480);
    __nv_bfloat16 (*sBl)[LB] = (__nv_bfloat16(*)[LB])(smem_raw + 25088);
    float (*Ep)[BN + 4] = (float(*)[BN + 4])smem_raw;

    int nb = blockIdx.x, rb = blockIdx.y, e = blockIdx.z;
    int base = 0, cnt = T_TOK;
    if (SCATTER) { base = g_offsets[e]; cnt = g_counts[e]; }
    int row0 = rb * BM;
    if (row0 >= cnt) return;
    int n0 = nb * BN;

    const float* w = W;
    if (SCATTER) w += (size_t)e * I_DIM * H_DIM;
    const float* act = (SCATTER ? g_act : g_shact) + (size_t)(base + row0) * LDA;

    int tid = threadIdx.x;
    int warp = tid >> 5;
    int rowOff = (warp >> 1) * 32, colOff = (warp & 1) * 32;

    int aR = tid >> 3, aC = (tid & 7) * 4;
    int bR = tid >> 4, bC = (tid & 15) * 4;
    const float* ap = act + (size_t)aR * LDA + aC;
    const float* bp = w + (size_t)bR * H_DIM + n0 + bC;

    float4 rA[4], rB[2];
    #pragma unroll
    for (int i = 0; i < 4; i++) rA[i] = *(const float4*)(ap + (size_t)(32 * i) * LDA);
    #pragma unroll
    for (int i = 0; i < 2; i++) rB[i] = *(const float4*)(bp + (size_t)(16 * i) * H_DIM);

    FragC acc[2][2];
    #pragma unroll
    for (int i = 0; i < 2; i++)
        #pragma unroll
        for (int j = 0; j < 2; j++) wmma::fill_fragment(acc[i][j], 0.f);

    for (int k0 = 0; k0 < KDIM; k0 += BK) {
        #pragma unroll
        for (int i = 0; i < 4; i++) {
            uint2 h, l; split4(rA[i], h, l);
            int r = aR + 32 * i;
            *(uint2*)&sAh[r][aC] = h;
            *(uint2*)&sAl[r][aC] = l;
        }
        #pragma unroll
        for (int i = 0; i < 2; i++) {
            uint2 h, l; split4(rB[i], h, l);
            int r = bR + 16 * i;
            *(uint2*)&sBh[r][bC] = h;
            *(uint2*)&sBl[r][bC] = l;
        }
        __syncthreads();

        int k1 = k0 + BK;
        if (k1 < KDIM) {
            #pragma unroll
            for (int i = 0; i < 4; i++)
                rA[i] = *(const float4*)(ap + (size_t)(32 * i) * LDA + k1);
            #pragma unroll
            for (int i = 0; i < 2; i++)
                rB[i] = *(const float4*)(bp + (size_t)(k1 + 16 * i) * H_DIM);
        }

        #pragma unroll
        for (int kk = 0; kk < BK; kk += 16) {
            FragA fah[2], fal[2];
            FragB fbh[2], fbl[2];
            #pragma unroll
            for (int i = 0; i < 2; i++) {
                wmma::load_matrix_sync(fah[i], &sAh[rowOff + 16 * i][kk], LA);
                wmma::load_matrix_sync(fal[i], &sAl[rowOff + 16 * i][kk], LA);
            }
            #pragma unroll
            for (int j = 0; j < 2; j++) {
                wmma::load_matrix_sync(fbh[j], &sBh[kk][colOff + 16 * j], LB);
                wmma::load_matrix_sync(fbl[j], &sBl[kk][colOff + 16 * j], LB);
            }
            #pragma unroll
            for (int i = 0; i < 2; i++)
                #pragma unroll
                for (int j = 0; j < 2; j++) {
                    wmma::mma_sync(acc[i][j], fah[i], fbh[j], acc[i][j]);
                    wmma::mma_sync(acc[i][j], fah[i], fbl[j], acc[i][j]);
                    wmma::mma_sync(acc[i][j], fal[i], fbh[j], acc[i][j]);
                }
        }
        __syncthreads();
    }

    // Epilogue: stage to smem, then per-row gated writeout
    #pragma unroll
    for (int i = 0; i < 2; i++)
        #pragma unroll
        for (int j = 0; j < 2; j++)
            wmma::store_matrix_sync(&Ep[rowOff + 16 * i][colOff + 16 * j],
                                    acc[i][j], BN + 4, wmma::mem_row_major);
    __syncthreads();
    #pragma unroll
    for (int i = 0; i < 8; i++) {
        int lin = tid + i * 256;          // 128 rows x 16 float4
        int r = lin >> 4, c4 = lin & 15;
        int local = row0 + r;
        if (SCATTER) {
            if (local < cnt) {
                int a = g_perm[base + local];
                *(float4*)(g_ya + (size_t)a * H_DIM + n0 + c4 * 4) = *(float4*)&Ep[r][c4 * 4];
            }
        } else {
            *(float4*)(OutP + (size_t)local * H_DIM + n0 + c4 * 4) = *(float4*)&Ep[r][c4 * 4];
        }
    }
}

// out[t] = shared_out[t] (already there) + sum_k w[t,k] * ya[t*4+k]
__global__ void k_combine(float* __restrict__ Out) {
    int lin = blockIdx.x * 256 + threadIdx.x;   // float4 index
    int t  = lin >> 8;                           // H/4 = 256 float4 per token
    int c4 = lin & 255;
    float4 acc = ((float4*)Out)[lin];
    #pragma unroll
    for (int k = 0; k < TOPK; k++) {
        float wv = g_topk_w[t * TOPK + k];
        float4 v = *(const float4*)(g_ya + (size_t)(t * TOPK + k) * H_DIM + c4 * 4);
        acc.x += wv * v.x; acc.y += wv * v.y; acc.z += wv * v.z; acc.w += wv * v.w;
    }
    ((float4*)Out)[lin] = acc;
}

// ---------------- launch ----------------
extern "C" void kernel_launch(void* const* d_in, const int* in_sizes, int n_in,
                              void* d_out, int out_size)
{
    const float* x  = (const float*)d_in[0];   // [1,2048,1024]
    const float* gw = (const float*)d_in[1];   // [16,1024]
    const float* eg = (const float*)d_in[2];   // [16,1024,512]
    const float* eu = (const float*)d_in[3];   // [16,1024,512]
    const float* ed = (const float*)d_in[4];   // [16,512,1024]
    const float* sg = (const float*)d_in[5];   // [1024,1024]
    const float* su = (const float*)d_in[6];   // [1024,1024]
    const float* sd = (const float*)d_in[7];   // [1024,1024]
    float* out = (float*)d_out;

    k_init<<<1, 32>>>();
    k_gate<<<T_TOK, 128>>>(x, gw);
    k_offsets<<<1, 1>>>();
    k_scatter<<<T_TOK / 256, 256>>>();

    // routed SwiGLU: grid (I/64, up-to-2048-rows/128, E)
    k_swiglu_gemm<true,  I_DIM ><<<dim3(I_DIM  / 64, 16,          N_EXP), 256>>>(x, eg, eu);
    // shared SwiGLU
    k_swiglu_gemm<false, SI_DIM><<<dim3(SI_DIM / 64, T_TOK / 128, 1    ), 256>>>(x, sg, su);

    // routed down -> scatter rows into g_ya
    k_down_gemm<true,  I_DIM,  I_DIM ><<<dim3(H_DIM / 64, 16,          N_EXP), 256>>>(ed, nullptr);
    // shared down -> writes d_out (covers every element)
    k_down_gemm<false, SI_DIM, SI_DIM><<<dim3(H_DIM / 64, T_TOK / 128, 1    ), 256>>>(sd, out);

    k_combine<<<(T_TOK * H_DIM / 4) / 256, 256>>>(out);
}